// round 14
// baseline (speedup 1.0000x reference)
#include <cuda_runtime.h>
#include <cstdint>

// YOLO layer: x (64, 255, 44, 44) f32 -> out (64, 5808, 85) f32.
//   out[b, a*1936 + s, c] = f(x[b, a*85 + c, s])
//   c==0:(sig+gx)*8  c==1:(sig+gy)*8  c==2:exp*aw  c==3:exp*ah  c>=4:sig
//
// R14 = R13 champion body (front-batched MLP=6 reads, 35.3us, DRAM 70%)
// with the per-tile TMA drain stall halved: each CTA owns TWO adjacent
// s-tiles and two smem buffers. commit(tile0) without waiting, read tile1
// while tile0's 43.5KB bulk write drains, commit(tile1), single
// wait_group.read 0 before exit. No per-iteration wait-gates (the R7/R11
// mistake). 2 x 43,520B smem -> 2 CTAs/SM, 32 warps x MLP6 = 192 LDG.128
// in flight per SM (>= R13's achieved ~35-warp concurrency).
// Read: warp-per-channel LDG.128 along s, STS.32 x4 into output-layout smem
//       [sl*85+ch] (stride-85: conflict-free).
// Sigmoid: 4-instruction approx (FMUL, MUFU.EX2, FADD, MUFU.RCP).

#define G44   44
#define GG    1936
#define CH    85
#define NA    3
#define TS    128
#define NTHR  512
#define NWARP 16
#define TILE_F (TS * CH)

__constant__ float c_aw[NA] = {10.0f, 16.0f, 33.0f};   // scaled_anchor*STRIDE
__constant__ float c_ah[NA] = {13.0f, 30.0f, 23.0f};

__device__ __forceinline__ float sig_(float v) {
    float e;
    asm("ex2.approx.ftz.f32 %0, %1;" : "=f"(e) : "f"(v * -1.442695041f));
    float r;
    asm("rcp.approx.ftz.f32 %0, %1;" : "=f"(r) : "f"(1.0f + e));
    return r;
}

__device__ __forceinline__ float exp_(float v) {
    float e;
    asm("ex2.approx.ftz.f32 %0, %1;" : "=f"(e) : "f"(v * 1.442695041f));
    return e;
}

extern __shared__ float smbuf[];   // 2 * TILE_F floats = 87,040 B

// process one 128-position tile into the given smem buffer, then commit a
// bulk write WITHOUT waiting.
__device__ __forceinline__ void do_tile(
    const float* __restrict__ x, float* __restrict__ out,
    float* __restrict__ sm, int ba, int a, int s0,
    int warp, int lane)
{
    const int valid = min(TS, GG - s0);           // 128, or 16 on last tile
    const int sl = lane << 2;

    if (sl < valid) {
        const float* __restrict__ ib = x + (size_t)ba * (CH * GG) + (s0 + sl);
        float* __restrict__ row = sm + sl * CH;

        // ---- front-batch: 6 independent LDG.128 before any math ----
        float4 v0, v1, v2, v3, v4, v5;
        v0 = *(const float4*)(ib + (size_t)(warp + 0 * NWARP) * GG);
        v1 = *(const float4*)(ib + (size_t)(warp + 1 * NWARP) * GG);
        v2 = *(const float4*)(ib + (size_t)(warp + 2 * NWARP) * GG);
        v3 = *(const float4*)(ib + (size_t)(warp + 3 * NWARP) * GG);
        v4 = *(const float4*)(ib + (size_t)(warp + 4 * NWARP) * GG);
        if (warp < 5)
            v5 = *(const float4*)(ib + (size_t)(warp + 5 * NWARP) * GG);

        // ---- ch = warp (0..15): specials live only here (warp-uniform) ----
        {
            const int ch = warp;
            float t0, t1, t2, t3;
            if (ch >= 4) {
                t0 = sig_(v0.x); t1 = sig_(v0.y);
                t2 = sig_(v0.z); t3 = sig_(v0.w);
            } else if (ch == 0) {
                const int s  = s0 + sl;
                const int gx = s - (s / G44) * G44;   // s%4==0, 44%4==0
                t0 = (sig_(v0.x) + (float)(gx + 0)) * 8.0f;
                t1 = (sig_(v0.y) + (float)(gx + 1)) * 8.0f;
                t2 = (sig_(v0.z) + (float)(gx + 2)) * 8.0f;
                t3 = (sig_(v0.w) + (float)(gx + 3)) * 8.0f;
            } else if (ch == 1) {
                const float fy = (float)((s0 + sl) / G44);
                t0 = (sig_(v0.x) + fy) * 8.0f;
                t1 = (sig_(v0.y) + fy) * 8.0f;
                t2 = (sig_(v0.z) + fy) * 8.0f;
                t3 = (sig_(v0.w) + fy) * 8.0f;
            } else if (ch == 2) {
                const float aw = c_aw[a];
                t0 = exp_(v0.x) * aw; t1 = exp_(v0.y) * aw;
                t2 = exp_(v0.z) * aw; t3 = exp_(v0.w) * aw;
            } else {                              // ch == 3
                const float ah = c_ah[a];
                t0 = exp_(v0.x) * ah; t1 = exp_(v0.y) * ah;
                t2 = exp_(v0.z) * ah; t3 = exp_(v0.w) * ah;
            }
            row[0 * CH + ch] = t0;
            row[1 * CH + ch] = t1;
            row[2 * CH + ch] = t2;
            row[3 * CH + ch] = t3;
        }

        // ---- remaining channels: pure sigmoid ----
        {
            const int ch = warp + 1 * NWARP;
            row[0 * CH + ch] = sig_(v1.x); row[1 * CH + ch] = sig_(v1.y);
            row[2 * CH + ch] = sig_(v1.z); row[3 * CH + ch] = sig_(v1.w);
        }
        {
            const int ch = warp + 2 * NWARP;
            row[0 * CH + ch] = sig_(v2.x); row[1 * CH + ch] = sig_(v2.y);
            row[2 * CH + ch] = sig_(v2.z); row[3 * CH + ch] = sig_(v2.w);
        }
        {
            const int ch = warp + 3 * NWARP;
            row[0 * CH + ch] = sig_(v3.x); row[1 * CH + ch] = sig_(v3.y);
            row[2 * CH + ch] = sig_(v3.z); row[3 * CH + ch] = sig_(v3.w);
        }
        {
            const int ch = warp + 4 * NWARP;
            row[0 * CH + ch] = sig_(v4.x); row[1 * CH + ch] = sig_(v4.y);
            row[2 * CH + ch] = sig_(v4.z); row[3 * CH + ch] = sig_(v4.w);
        }
        if (warp < 5) {
            const int ch = warp + 5 * NWARP;      // 80..84
            row[0 * CH + ch] = sig_(v5.x); row[1 * CH + ch] = sig_(v5.y);
            row[2 * CH + ch] = sig_(v5.z); row[3 * CH + ch] = sig_(v5.w);
        }
    }

    __syncthreads();

    // ---- commit bulk write, NO wait (overlaps the next tile's reads) ----
    if (threadIdx.x == 0) {
        uint32_t saddr;
        asm volatile("{ .reg .u64 t; cvta.to.shared.u64 t, %1; cvt.u32.u64 %0, t; }"
                     : "=r"(saddr) : "l"(sm));
        float* gptr = out + ((size_t)ba * GG + s0) * CH;   // 16B-aligned
        const uint32_t bytes = (uint32_t)(valid * CH * 4); // multiple of 16

        asm volatile("fence.proxy.async.shared::cta;" ::: "memory");
        asm volatile("cp.async.bulk.global.shared::cta.bulk_group [%0], [%1], %2;"
                     :: "l"(gptr), "r"(saddr), "r"(bytes) : "memory");
        asm volatile("cp.async.bulk.commit_group;" ::: "memory");
    }
}

__global__ __launch_bounds__(NTHR, 2)
void yolo_kernel(const float* __restrict__ x, float* __restrict__ out) {
    const int ba   = blockIdx.y;                  // b*NA + a (0..191)
    const int a    = ba % NA;
    const int warp = threadIdx.x >> 5;
    const int lane = threadIdx.x & 31;

    // this CTA owns s-tiles 2*bx and 2*bx+1
    const int s0 = (blockIdx.x << 1) * TS;

    do_tile(x, out, smbuf,          ba, a, s0,      warp, lane);
    // no wait: tile0's write drains while tile1 is read/transformed
    do_tile(x, out, smbuf + TILE_F, ba, a, s0 + TS, warp, lane);

    // single drain before exit (smem must stay alive for pending TMA reads)
    if (threadIdx.x == 0)
        asm volatile("cp.async.bulk.wait_group.read 0;" ::: "memory");
}

extern "C" void kernel_launch(void* const* d_in, const int* in_sizes, int n_in,
                              void* d_out, int out_size) {
    const float* x = (const float*)d_in[0];
    float* out = (float*)d_out;

    static const size_t shmem = 2 * TILE_F * sizeof(float);   // 87,040 B
    static bool configured = false;
    if (!configured) {
        cudaFuncSetAttribute(yolo_kernel,
                             cudaFuncAttributeMaxDynamicSharedMemorySize,
                             (int)shmem);
        configured = true;
    }

    dim3 grid(8,            // 8 tile-pairs = 16 s-tiles
              64 * NA);     // 192 (b,a) matrices
    yolo_kernel<<<grid, NTHR, shmem>>>(x, out);
}

// round 15
// speedup vs baseline: 1.0390x; 1.0390x over previous
#include <cuda_runtime.h>
#include <cstdint>

// YOLO layer: x (64, 255, 44, 44) f32 -> out (64, 5808, 85) f32.
//   out[b, a*1936 + s, c] = f(x[b, a*85 + c, s])
//   c==0:(sig+gx)*8  c==1:(sig+gy)*8  c==2:exp*aw  c==3:exp*ah  c>=4:sig
//
// R15 = R13 (champion: front-batched MLP=6, 35.3us, DRAM 70%) + TS=112:
// smem/CTA 43,520 -> 38,080 B so 3 CTAs = 114KB sits WELL inside the default
// shared tier (R13's 130.6KB was at the edge; achieved occ only 55%).
// Stacks full 48-warp residency on top of MLP=6 per thread.
// Read: warp-per-channel LDG.128 along s (lanes 0..25), 6 loads front-
//       batched, STS.32 x4 into output-layout smem [sl*85+ch] (stride-85:
//       conflict-free).
// Write: ONE cp.async.bulk (shared->global) per tile, contiguous 35,360 B.
// Sigmoid: 4-instruction approx (FMUL, MUFU.EX2, FADD, MUFU.RCP).

#define G44   44
#define GG    1936
#define CH    85
#define NA    3
#define TS    112
#define NTHR  512
#define NWARP 16
#define NTILE 18              // ceil(1936/112): 17 full + tail of 64

__constant__ float c_aw[NA] = {10.0f, 16.0f, 33.0f};   // scaled_anchor*STRIDE
__constant__ float c_ah[NA] = {13.0f, 30.0f, 23.0f};

__device__ __forceinline__ float sig_(float v) {
    float e;
    asm("ex2.approx.ftz.f32 %0, %1;" : "=f"(e) : "f"(v * -1.442695041f));
    float r;
    asm("rcp.approx.ftz.f32 %0, %1;" : "=f"(r) : "f"(1.0f + e));
    return r;
}

__device__ __forceinline__ float exp_(float v) {
    float e;
    asm("ex2.approx.ftz.f32 %0, %1;" : "=f"(e) : "f"(v * 1.442695041f));
    return e;
}

__global__ __launch_bounds__(NTHR, 3)
void yolo_kernel(const float* __restrict__ x, float* __restrict__ out) {
    __shared__ __align__(16) float sm[TS * CH];   // 38,080 B, output layout

    const int ba   = blockIdx.y;                  // b*NA + a (0..191)
    const int a    = ba % NA;
    const int s0   = blockIdx.x * TS;
    const int warp = threadIdx.x >> 5;
    const int lane = threadIdx.x & 31;
    const int valid = min(TS, GG - s0);           // 112, or 64 on last tile

    const int sl = lane << 2;                     // lanes 26..31 idle (sl>=104)
    if (sl < valid) {
        const float* __restrict__ ib = x + (size_t)ba * (CH * GG) + (s0 + sl);
        float* __restrict__ row = sm + sl * CH;

        // ---- front-batch: 6 independent LDG.128 before any math ----
        float4 v0, v1, v2, v3, v4, v5;
        v0 = *(const float4*)(ib + (size_t)(warp + 0 * NWARP) * GG);
        v1 = *(const float4*)(ib + (size_t)(warp + 1 * NWARP) * GG);
        v2 = *(const float4*)(ib + (size_t)(warp + 2 * NWARP) * GG);
        v3 = *(const float4*)(ib + (size_t)(warp + 3 * NWARP) * GG);
        v4 = *(const float4*)(ib + (size_t)(warp + 4 * NWARP) * GG);
        if (warp < 5)
            v5 = *(const float4*)(ib + (size_t)(warp + 5 * NWARP) * GG);

        // ---- ch = warp (0..15): special cases live only here ----
        {
            const int ch = warp;
            float t0, t1, t2, t3;
            if (ch >= 4) {                        // warp-uniform
                t0 = sig_(v0.x); t1 = sig_(v0.y);
                t2 = sig_(v0.z); t3 = sig_(v0.w);
            } else if (ch == 0) {
                const int s  = s0 + sl;           // s%4==0 (112%4==0)
                const int gx = s - (s / G44) * G44;   // gx%4==0 -> gx+3<=43
                t0 = (sig_(v0.x) + (float)(gx + 0)) * 8.0f;
                t1 = (sig_(v0.y) + (float)(gx + 1)) * 8.0f;
                t2 = (sig_(v0.z) + (float)(gx + 2)) * 8.0f;
                t3 = (sig_(v0.w) + (float)(gx + 3)) * 8.0f;
            } else if (ch == 1) {
                const float fy = (float)((s0 + sl) / G44);
                t0 = (sig_(v0.x) + fy) * 8.0f;
                t1 = (sig_(v0.y) + fy) * 8.0f;
                t2 = (sig_(v0.z) + fy) * 8.0f;
                t3 = (sig_(v0.w) + fy) * 8.0f;
            } else if (ch == 2) {
                const float aw = c_aw[a];
                t0 = exp_(v0.x) * aw; t1 = exp_(v0.y) * aw;
                t2 = exp_(v0.z) * aw; t3 = exp_(v0.w) * aw;
            } else {                              // ch == 3
                const float ah = c_ah[a];
                t0 = exp_(v0.x) * ah; t1 = exp_(v0.y) * ah;
                t2 = exp_(v0.z) * ah; t3 = exp_(v0.w) * ah;
            }
            row[0 * CH + ch] = t0;
            row[1 * CH + ch] = t1;
            row[2 * CH + ch] = t2;
            row[3 * CH + ch] = t3;
        }

        // ---- remaining channels: pure sigmoid ----
        {
            const int ch = warp + 1 * NWARP;
            row[0 * CH + ch] = sig_(v1.x); row[1 * CH + ch] = sig_(v1.y);
            row[2 * CH + ch] = sig_(v1.z); row[3 * CH + ch] = sig_(v1.w);
        }
        {
            const int ch = warp + 2 * NWARP;
            row[0 * CH + ch] = sig_(v2.x); row[1 * CH + ch] = sig_(v2.y);
            row[2 * CH + ch] = sig_(v2.z); row[3 * CH + ch] = sig_(v2.w);
        }
        {
            const int ch = warp + 3 * NWARP;
            row[0 * CH + ch] = sig_(v3.x); row[1 * CH + ch] = sig_(v3.y);
            row[2 * CH + ch] = sig_(v3.z); row[3 * CH + ch] = sig_(v3.w);
        }
        {
            const int ch = warp + 4 * NWARP;
            row[0 * CH + ch] = sig_(v4.x); row[1 * CH + ch] = sig_(v4.y);
            row[2 * CH + ch] = sig_(v4.z); row[3 * CH + ch] = sig_(v4.w);
        }
        if (warp < 5) {
            const int ch = warp + 5 * NWARP;      // 80..84
            row[0 * CH + ch] = sig_(v5.x); row[1 * CH + ch] = sig_(v5.y);
            row[2 * CH + ch] = sig_(v5.z); row[3 * CH + ch] = sig_(v5.w);
        }
    }

    __syncthreads();

    // ---- write: single bulk async copy smem -> gmem (contiguous tile) ----
    if (threadIdx.x == 0) {
        uint32_t saddr;
        asm volatile("{ .reg .u64 t; cvta.to.shared.u64 t, %1; cvt.u32.u64 %0, t; }"
                     : "=r"(saddr) : "l"(sm));
        float* gptr = out + ((size_t)ba * GG + s0) * CH;   // 16B-aligned
        const uint32_t bytes = (uint32_t)(valid * CH * 4); // multiple of 16

        asm volatile("fence.proxy.async.shared::cta;" ::: "memory");
        asm volatile("cp.async.bulk.global.shared::cta.bulk_group [%0], [%1], %2;"
                     :: "l"(gptr), "r"(saddr), "r"(bytes) : "memory");
        asm volatile("cp.async.bulk.commit_group;" ::: "memory");
        asm volatile("cp.async.bulk.wait_group.read 0;" ::: "memory");
    }
}

extern "C" void kernel_launch(void* const* d_in, const int* in_sizes, int n_in,
                              void* d_out, int out_size) {
    const float* x = (const float*)d_in[0];
    float* out = (float*)d_out;

    dim3 grid(NTILE,        // 18 spatial tiles (17 full + tail of 64)
              64 * NA);     // 192 (b,a) matrices
    yolo_kernel<<<grid, NTHR>>>(x, out);
}